// round 1
// baseline (speedup 1.0000x reference)
#include <cuda_runtime.h>
#include <math_constants.h>

#define DIN 14
#define QN  256
#define SB  16
#define NC  7

typedef unsigned long long u64;

// ---- device scratch (no allocations allowed) ----
__device__ float2 g_kdup[QN * DIN];   // LN'd stored patterns, duplicated (k,k)
__device__ float  g_vln[QN * DIN];    // LN'd pattern-projection input
__device__ float  g_c8[QN * 8];       // c[j][n] = Wm@(Wo@(Wv@vln_j)), padded to 8

// ---- packed f32x2 helpers (Blackwell dual-rate FP32) ----
__device__ __forceinline__ u64 fma2(u64 a, u64 b, u64 c) {
    u64 d;
    asm("fma.rn.f32x2 %0, %1, %2, %3;" : "=l"(d) : "l"(a), "l"(b), "l"(c));
    return d;
}
__device__ __forceinline__ u64 pack2(float lo, float hi) {
    u64 r; asm("mov.b64 %0, {%1, %2};" : "=l"(r) : "f"(lo), "f"(hi)); return r;
}
__device__ __forceinline__ void unpack2(u64 v, float& lo, float& hi) {
    asm("mov.b64 {%0, %1}, %2;" : "=f"(lo), "=f"(hi) : "l"(v));
}

// ============================================================
// Prep A: LayerNorm the 256 stored patterns (two LN variants)
// ============================================================
__global__ void prep_ln(const float* __restrict__ lookup,
                        const float* __restrict__ g_st, const float* __restrict__ b_st,
                        const float* __restrict__ g_pp, const float* __restrict__ b_pp) {
    int j = threadIdx.x;
    if (j >= QN) return;
    float v[DIN];
    float mu = 0.f;
    #pragma unroll
    for (int d = 0; d < DIN; d++) { v[d] = lookup[j * DIN + d]; mu += v[d]; }
    mu *= (1.0f / DIN);
    float var = 0.f;
    #pragma unroll
    for (int d = 0; d < DIN; d++) { float dv = v[d] - mu; var += dv * dv; }
    float r = rsqrtf(var * (1.0f / DIN) + 1e-5f);
    #pragma unroll
    for (int d = 0; d < DIN; d++) {
        float c  = (v[d] - mu) * r;
        float kn = c * g_st[d] + b_st[d];
        g_kdup[j * DIN + d] = make_float2(kn, kn);
        g_vln[j * DIN + d]  = c * g_pp[d] + b_pp[d];
    }
}

// ============================================================
// Prep B: c8[j][n] = Wm @ (Wo @ (Wv @ vln_j)).  One block per j.
// ============================================================
__global__ void prep_c(const float* __restrict__ Wv, const float* __restrict__ Wo,
                       const float* __restrict__ Wm) {
    int j = blockIdx.x;
    __shared__ float sv[DIN];
    __shared__ float sp[256];
    __shared__ float shp[28][4];
    __shared__ float hh[28];
    int t = threadIdx.x;
    if (t < DIN) sv[t] = g_vln[j * DIN + t];
    __syncthreads();
    // p = Wv @ vln   (256)
    {
        float acc = 0.f;
        #pragma unroll
        for (int d = 0; d < DIN; d++) acc += Wv[t * DIN + d] * sv[d];
        sp[t] = acc;
    }
    __syncthreads();
    // h = Wo @ p     (28), 4-way split reduction
    if (t < 112) {
        int o = t >> 2, part = t & 3;
        float a = 0.f;
        int p0 = part * 64;
        #pragma unroll 8
        for (int p = p0; p < p0 + 64; p++) a += Wo[o * 256 + p] * sp[p];
        shp[o][part] = a;
    }
    __syncthreads();
    if (t < 28) hh[t] = shp[t][0] + shp[t][1] + shp[t][2] + shp[t][3];
    __syncthreads();
    // c = Wm @ h     (7, pad to 8)
    if (t < 8) {
        float a = 0.f;
        if (t < NC) {
            #pragma unroll
            for (int o = 0; o < 28; o++) a += Wm[t * 28 + o] * hh[o];
        }
        g_c8[j * 8 + t] = a;
    }
}

// ============================================================
// Main: per-query LN + argmax over 256 patterns + head fold
//   128 threads/block, 8 queries/thread (half a batch element)
//   queries packed pairwise into f32x2; k duplicated in SMEM so
//   one broadcast LDS.64 feeds 4 FFMA2 (8 scalar FMAs).
// ============================================================
__global__ __launch_bounds__(128) void hopfield_main(
    const float* __restrict__ x,
    const float* __restrict__ g_sp, const float* __restrict__ b_sp,
    const float* __restrict__ bm,   const float* __restrict__ Wb,
    const float* __restrict__ bb,
    float* __restrict__ out, int B)
{
    __shared__ u64   sk[QN * DIN];   // 28672 B, (k,k) pairs
    __shared__ float sc[QN * 8];     // 8192 B
    __shared__ float swb[SB];
    __shared__ float sg[DIN], sb[DIN];
    __shared__ float sbm[8];
    __shared__ float sbb;

    int t = threadIdx.x;
    {
        const u64* kg = (const u64*)g_kdup;
        for (int i = t; i < QN * DIN; i += 128) sk[i] = kg[i];
        for (int i = t; i < QN * 8;  i += 128) sc[i] = g_c8[i];
        if (t < SB)  swb[t] = Wb[t];
        if (t < DIN) { sg[t] = g_sp[t]; sb[t] = b_sp[t]; }
        if (t < NC)  sbm[t] = bm[t];
        if (t == 0)  { sbm[7] = 0.f; sbb = bb[0]; }
    }
    __syncthreads();

    int brow = blockIdx.x * 64 + (t >> 1);
    bool valid = (brow < B);
    int b = valid ? brow : (B - 1);
    int s0 = (t & 1) * 8;

    const float* xp = x + ((size_t)b * SB + s0) * DIN;

    // ---- LayerNorm 8 queries, pack pairwise into f32x2 ----
    u64 q2[4][DIN];
    #pragma unroll
    for (int pp = 0; pp < 4; pp++) {
        float qa[DIN], qb[DIN];
        #pragma unroll
        for (int half = 0; half < 2; half++) {
            float* q = half ? qb : qa;
            const float2* p2 = (const float2*)(xp + (2 * pp + half) * DIN);
            float v[DIN];
            #pragma unroll
            for (int i = 0; i < 7; i++) { float2 w = p2[i]; v[2*i] = w.x; v[2*i+1] = w.y; }
            float mu = 0.f;
            #pragma unroll
            for (int d = 0; d < DIN; d++) mu += v[d];
            mu *= (1.0f / DIN);
            float var = 0.f;
            #pragma unroll
            for (int d = 0; d < DIN; d++) { float dv = v[d] - mu; var += dv * dv; }
            float r = rsqrtf(var * (1.0f / DIN) + 1e-5f);
            #pragma unroll
            for (int d = 0; d < DIN; d++) q[d] = (v[d] - mu) * r * sg[d] + sb[d];
        }
        #pragma unroll
        for (int d = 0; d < DIN; d++) q2[pp][d] = pack2(qa[d], qb[d]);
    }

    // ---- argmax over 256 stored patterns ----
    float maxv[8]; int idx[8];
    #pragma unroll
    for (int p = 0; p < 8; p++) { maxv[p] = -CUDART_INF_F; idx[p] = 0; }

    #pragma unroll 2
    for (int j = 0; j < QN; j++) {
        const u64* kp = sk + j * DIN;
        u64 a0 = 0ull, a1 = 0ull, a2 = 0ull, a3 = 0ull;  // {0.f,0.f}
        #pragma unroll
        for (int d = 0; d < DIN; d++) {
            u64 kk = kp[d];                  // broadcast LDS.64
            a0 = fma2(kk, q2[0][d], a0);
            a1 = fma2(kk, q2[1][d], a1);
            a2 = fma2(kk, q2[2][d], a2);
            a3 = fma2(kk, q2[3][d], a3);
        }
        float lo, hi;
        unpack2(a0, lo, hi);
        if (lo > maxv[0]) { maxv[0] = lo; idx[0] = j; }
        if (hi > maxv[1]) { maxv[1] = hi; idx[1] = j; }
        unpack2(a1, lo, hi);
        if (lo > maxv[2]) { maxv[2] = lo; idx[2] = j; }
        if (hi > maxv[3]) { maxv[3] = hi; idx[3] = j; }
        unpack2(a2, lo, hi);
        if (lo > maxv[4]) { maxv[4] = lo; idx[4] = j; }
        if (hi > maxv[5]) { maxv[5] = hi; idx[5] = j; }
        unpack2(a3, lo, hi);
        if (lo > maxv[6]) { maxv[6] = lo; idx[6] = j; }
        if (hi > maxv[7]) { maxv[7] = hi; idx[7] = j; }
    }

    // ---- head: z[n] = sum_s Wb[s]*c[idx(s)][n] (+bias), softmax over 7 ----
    float zp[NC];
    #pragma unroll
    for (int n = 0; n < NC; n++) zp[n] = 0.f;
    #pragma unroll
    for (int p = 0; p < 8; p++) {
        // query p is band s0+p; pairs were (2pp, 2pp+1) -> p order is s-order
        int id = idx[p];
        float w = swb[s0 + p];
        const float* cr = sc + id * 8;
        #pragma unroll
        for (int n = 0; n < NC; n++) zp[n] += w * cr[n];
    }
    // combine the two half-batch threads (t and t^1, same b, same warp)
    #pragma unroll
    for (int n = 0; n < NC; n++) zp[n] += __shfl_xor_sync(0xffffffffu, zp[n], 1);

    if (valid && ((t & 1) == 0)) {
        float sumWb = 0.f;
        #pragma unroll
        for (int s = 0; s < SB; s++) sumWb += swb[s];
        float z[NC], zmax = -CUDART_INF_F;
        #pragma unroll
        for (int n = 0; n < NC; n++) {
            z[n] = zp[n] + sbm[n] * sumWb + sbb;
            zmax = fmaxf(zmax, z[n]);
        }
        float es = 0.f;
        #pragma unroll
        for (int n = 0; n < NC; n++) { z[n] = expf(z[n] - zmax); es += z[n]; }
        float inv = 1.0f / es;
        float* op = out + (size_t)b * NC;
        #pragma unroll
        for (int n = 0; n < NC; n++) op[n] = z[n] * inv;
    }
}

// ============================================================
extern "C" void kernel_launch(void* const* d_in, const int* in_sizes, int n_in,
                              void* d_out, int out_size) {
    const float* x      = (const float*)d_in[0];
    const float* lookup = (const float*)d_in[1];
    const float* g_st   = (const float*)d_in[2];
    const float* b_st   = (const float*)d_in[3];
    const float* g_sp   = (const float*)d_in[4];
    const float* b_sp   = (const float*)d_in[5];
    const float* g_pp   = (const float*)d_in[6];
    const float* b_pp   = (const float*)d_in[7];
    const float* Wv     = (const float*)d_in[8];
    const float* Wo     = (const float*)d_in[9];
    const float* Wm     = (const float*)d_in[10];
    const float* bm     = (const float*)d_in[11];
    const float* Wb     = (const float*)d_in[12];
    const float* bb     = (const float*)d_in[13];
    float* out = (float*)d_out;

    int B = in_sizes[0] / (SB * DIN);

    prep_ln<<<1, 256>>>(lookup, g_st, b_st, g_pp, b_pp);
    prep_c<<<QN, 256>>>(Wv, Wo, Wm);
    hopfield_main<<<(B + 63) / 64, 128>>>(x, g_sp, b_sp, bm, Wb, bb, out, B);
}

// round 3
// speedup vs baseline: 1.1129x; 1.1129x over previous
#include <cuda_runtime.h>
#include <math_constants.h>

#define DIN 14
#define QN  256
#define SB  16
#define NC  7

typedef unsigned long long u64;

// ---- device scratch (no allocations allowed) ----
__device__ float2 g_kdup[QN * DIN];   // LN'd stored patterns, duplicated (k,k)
__device__ float  g_c8[QN * 8];       // c[j][n] = Wm@(Wo@(Wv@LNpp(lookup_j))), padded to 8

// ---- packed f32x2 helpers (Blackwell dual-rate FP32, FFMA2) ----
__device__ __forceinline__ u64 fma2(u64 a, u64 b, u64 c) {
    u64 d;
    asm("fma.rn.f32x2 %0, %1, %2, %3;" : "=l"(d) : "l"(a), "l"(b), "l"(c));
    return d;
}
__device__ __forceinline__ u64 pack2(float lo, float hi) {
    u64 r; asm("mov.b64 %0, {%1, %2};" : "=l"(r) : "f"(lo), "f"(hi)); return r;
}
__device__ __forceinline__ void unpack2(u64 v, float& lo, float& hi) {
    asm("mov.b64 {%0, %1}, %2;" : "=f"(lo), "=f"(hi) : "l"(v));
}

// ============================================================
// Fused prep: block j LayerNorms pattern j (both LN variants),
// then computes c8[j] = Wm@(Wo@(Wv@vln_j)) and writes g_kdup[j].
// ============================================================
__global__ __launch_bounds__(128) void prep_all(
    const float* __restrict__ lookup,
    const float* __restrict__ g_st, const float* __restrict__ b_st,
    const float* __restrict__ g_pp, const float* __restrict__ b_pp,
    const float* __restrict__ Wv,   const float* __restrict__ Wo,
    const float* __restrict__ Wm)
{
    int j = blockIdx.x;
    int t = threadIdx.x;
    __shared__ float sv[DIN];       // vln_j
    __shared__ float sp[256];       // Wv @ vln
    __shared__ float shp[28][4];
    __shared__ float hh[28];

    // LN (every thread computes redundantly; thread<DIN writes)
    {
        float v[DIN];
        float mu = 0.f;
        #pragma unroll
        for (int d = 0; d < DIN; d++) { v[d] = lookup[j * DIN + d]; mu += v[d]; }
        mu *= (1.0f / DIN);
        float var = 0.f;
        #pragma unroll
        for (int d = 0; d < DIN; d++) { float dv = v[d] - mu; var += dv * dv; }
        float r = rsqrtf(var * (1.0f / DIN) + 1e-5f);
        if (t < DIN) {
            float c  = (v[t] - mu) * r;
            float kn = c * g_st[t] + b_st[t];
            g_kdup[j * DIN + t] = make_float2(kn, kn);
            sv[t] = c * g_pp[t] + b_pp[t];
        }
    }
    __syncthreads();

    // p = Wv @ vln  (256 outputs, 2 per thread)
    #pragma unroll
    for (int rr = 0; rr < 2; rr++) {
        int row = t + rr * 128;
        float acc = 0.f;
        #pragma unroll
        for (int d = 0; d < DIN; d++) acc += Wv[row * DIN + d] * sv[d];
        sp[row] = acc;
    }
    __syncthreads();

    // h = Wo @ p  (28 outputs, 4-way split)
    if (t < 112) {
        int o = t >> 2, part = t & 3;
        float a = 0.f;
        int p0 = part * 64;
        #pragma unroll 8
        for (int p = p0; p < p0 + 64; p++) a += Wo[o * 256 + p] * sp[p];
        shp[o][part] = a;
    }
    __syncthreads();
    if (t < 28) hh[t] = shp[t][0] + shp[t][1] + shp[t][2] + shp[t][3];
    __syncthreads();

    // c = Wm @ h  (7 outputs, pad to 8)
    if (t < 8) {
        float a = 0.f;
        if (t < NC) {
            #pragma unroll
            for (int o = 0; o < 28; o++) a += Wm[t * 28 + o] * hh[o];
        }
        g_c8[j * 8 + t] = a;
    }
}

// ============================================================
// Main: 128 threads/block, 32 batch rows/block, 4 queries/thread.
// Queries pairwise-packed into f32x2; k duplicated (k,k) in SMEM
// so one LDS.128 (two (k,k) pairs) feeds 4 FFMA2.
// ============================================================
__global__ __launch_bounds__(128) void hopfield_main(
    const float* __restrict__ x,
    const float* __restrict__ g_sp, const float* __restrict__ b_sp,
    const float* __restrict__ bm,   const float* __restrict__ Wb,
    const float* __restrict__ bb,
    float* __restrict__ out, int B)
{
    __shared__ u64   sk[QN * DIN];   // 28672 B, (k,k) pairs
    __shared__ float sc[QN * 8];     // 8192 B
    __shared__ float swb[SB];
    __shared__ float sg[DIN], sb[DIN];
    __shared__ float sbm[8];
    __shared__ float sbb;

    int t = threadIdx.x;
    {
        const u64* kg = (const u64*)g_kdup;
        for (int i = t; i < QN * DIN; i += 128) sk[i] = kg[i];
        for (int i = t; i < QN * 8;  i += 128) sc[i] = g_c8[i];
        if (t < SB)  swb[t] = Wb[t];
        if (t < DIN) { sg[t] = g_sp[t]; sb[t] = b_sp[t]; }
        if (t < NC)  sbm[t] = bm[t];
        if (t == 0)  { sbm[7] = 0.f; sbb = bb[0]; }
    }
    __syncthreads();

    int brow = blockIdx.x * 32 + (t >> 2);
    bool valid = (brow < B);
    int b = valid ? brow : (B - 1);
    int s0 = (t & 3) * 4;                 // 4 consecutive bands per thread

    const float* xp = x + ((size_t)b * SB + s0) * DIN;

    // ---- LayerNorm 4 queries, pack pairwise into f32x2 ----
    u64 q2[2][DIN];
    #pragma unroll
    for (int pp = 0; pp < 2; pp++) {
        float qa[DIN], qb[DIN];
        #pragma unroll
        for (int half = 0; half < 2; half++) {
            float* q = half ? qb : qa;
            const float2* p2 = (const float2*)(xp + (2 * pp + half) * DIN);
            float v[DIN];
            #pragma unroll
            for (int i = 0; i < 7; i++) { float2 w = p2[i]; v[2*i] = w.x; v[2*i+1] = w.y; }
            float mu = 0.f;
            #pragma unroll
            for (int d = 0; d < DIN; d++) mu += v[d];
            mu *= (1.0f / DIN);
            float var = 0.f;
            #pragma unroll
            for (int d = 0; d < DIN; d++) { float dv = v[d] - mu; var += dv * dv; }
            float r = rsqrtf(var * (1.0f / DIN) + 1e-5f);
            #pragma unroll
            for (int d = 0; d < DIN; d++) q[d] = (v[d] - mu) * r * sg[d] + sb[d];
        }
        #pragma unroll
        for (int d = 0; d < DIN; d++) q2[pp][d] = pack2(qa[d], qb[d]);
    }

    // ---- argmax over 256 stored patterns ----
    float maxv[4]; int idx[4];
    #pragma unroll
    for (int p = 0; p < 4; p++) { maxv[p] = -CUDART_INF_F; idx[p] = 0; }

    const u64 z2 = pack2(0.f, 0.f);

    #pragma unroll 4
    for (int j = 0; j < QN; j++) {
        const ulonglong2* kp = (const ulonglong2*)(sk + j * DIN);
        u64 a0 = z2, a1 = z2;
        #pragma unroll
        for (int i = 0; i < 7; i++) {
            ulonglong2 kk = kp[i];            // LDS.128 broadcast: dims 2i,2i+1
            a0 = fma2(kk.x, q2[0][2*i],   a0);
            a1 = fma2(kk.x, q2[1][2*i],   a1);
            a0 = fma2(kk.y, q2[0][2*i+1], a0);
            a1 = fma2(kk.y, q2[1][2*i+1], a1);
        }
        float lo, hi;
        unpack2(a0, lo, hi);
        if (lo > maxv[0]) { maxv[0] = lo; idx[0] = j; }
        if (hi > maxv[1]) { maxv[1] = hi; idx[1] = j; }
        unpack2(a1, lo, hi);
        if (lo > maxv[2]) { maxv[2] = lo; idx[2] = j; }
        if (hi > maxv[3]) { maxv[3] = hi; idx[3] = j; }
    }

    // ---- head: z[n] = sum_s Wb[s]*c[idx(s)][n] (+bias), softmax over 7 ----
    float zp[NC];
    #pragma unroll
    for (int n = 0; n < NC; n++) zp[n] = 0.f;
    #pragma unroll
    for (int p = 0; p < 4; p++) {
        int id = idx[p];
        float w = swb[s0 + p];
        const float* cr = sc + id * 8;
        #pragma unroll
        for (int n = 0; n < NC; n++) zp[n] += w * cr[n];
    }
    // combine the 4 quarter-row threads (t..t^3, same b, same warp)
    #pragma unroll
    for (int n = 0; n < NC; n++) {
        zp[n] += __shfl_xor_sync(0xffffffffu, zp[n], 1);
        zp[n] += __shfl_xor_sync(0xffffffffu, zp[n], 2);
    }

    if (valid && ((t & 3) == 0)) {
        float sumWb = 0.f;
        #pragma unroll
        for (int s = 0; s < SB; s++) sumWb += swb[s];
        float z[NC], zmax = -CUDART_INF_F;
        #pragma unroll
        for (int n = 0; n < NC; n++) {
            z[n] = zp[n] + sbm[n] * sumWb + sbb;
            zmax = fmaxf(zmax, z[n]);
        }
        float es = 0.f;
        #pragma unroll
        for (int n = 0; n < NC; n++) { z[n] = expf(z[n] - zmax); es += z[n]; }
        float inv = 1.0f / es;
        float* op = out + (size_t)b * NC;
        #pragma unroll
        for (int n = 0; n < NC; n++) op[n] = z[n] * inv;
    }
}

// ============================================================
extern "C" void kernel_launch(void* const* d_in, const int* in_sizes, int n_in,
                              void* d_out, int out_size) {
    const float* x      = (const float*)d_in[0];
    const float* lookup = (const float*)d_in[1];
    const float* g_st   = (const float*)d_in[2];
    const float* b_st   = (const float*)d_in[3];
    const float* g_sp   = (const float*)d_in[4];
    const float* b_sp   = (const float*)d_in[5];
    const float* g_pp   = (const float*)d_in[6];
    const float* b_pp   = (const float*)d_in[7];
    const float* Wv     = (const float*)d_in[8];
    const float* Wo     = (const float*)d_in[9];
    const float* Wm     = (const float*)d_in[10];
    const float* bm     = (const float*)d_in[11];
    const float* Wb     = (const float*)d_in[12];
    const float* bb     = (const float*)d_in[13];
    float* out = (float*)d_out;

    int B = in_sizes[0] / (SB * DIN);

    prep_all<<<QN, 128>>>(lookup, g_st, b_st, g_pp, b_pp, Wv, Wo, Wm);
    hopfield_main<<<(B + 31) / 32, 128>>>(x, g_sp, b_sp, bm, Wb, bb, out, B);
}

// round 5
// speedup vs baseline: 1.1639x; 1.0458x over previous
#include <cuda_runtime.h>
#include <math_constants.h>

#define DIN 14
#define QN  256
#define SB  16
#define NC  7

typedef unsigned long long u64;

// ---- device scratch (no allocations allowed) ----
__device__ float2 g_kdup[QN * DIN];   // LN'd stored patterns, duplicated (k,k)
__device__ float  g_c8[QN * 8];       // c[j][n] = Wm@(Wo@(Wv@LNpp(lookup_j))), padded to 8

// ---- packed f32x2 helpers (Blackwell dual-rate FP32, FFMA2) ----
__device__ __forceinline__ u64 fma2(u64 a, u64 b, u64 c) {
    u64 d;
    asm("fma.rn.f32x2 %0, %1, %2, %3;" : "=l"(d) : "l"(a), "l"(b), "l"(c));
    return d;
}
__device__ __forceinline__ u64 pack2(float lo, float hi) {
    u64 r; asm("mov.b64 %0, {%1, %2};" : "=l"(r) : "f"(lo), "f"(hi)); return r;
}
__device__ __forceinline__ void unpack2(u64 v, float& lo, float& hi) {
    asm("mov.b64 {%0, %1}, %2;" : "=f"(lo), "=f"(hi) : "l"(v));
}

// ============================================================
// Fused prep: block j LayerNorms pattern j (both LN variants),
// then computes c8[j] = Wm@(Wo@(Wv@vln_j)) and writes g_kdup[j].
// ============================================================
__global__ __launch_bounds__(128) void prep_all(
    const float* __restrict__ lookup,
    const float* __restrict__ g_st, const float* __restrict__ b_st,
    const float* __restrict__ g_pp, const float* __restrict__ b_pp,
    const float* __restrict__ Wv,   const float* __restrict__ Wo,
    const float* __restrict__ Wm)
{
    int j = blockIdx.x;
    int t = threadIdx.x;
    __shared__ float sv[DIN];       // vln_j
    __shared__ float sp[256];       // Wv @ vln
    __shared__ float shp[28][4];
    __shared__ float hh[28];

    // LN (every thread computes redundantly; thread<DIN writes)
    {
        float v[DIN];
        float mu = 0.f;
        #pragma unroll
        for (int d = 0; d < DIN; d++) { v[d] = lookup[j * DIN + d]; mu += v[d]; }
        mu *= (1.0f / DIN);
        float var = 0.f;
        #pragma unroll
        for (int d = 0; d < DIN; d++) { float dv = v[d] - mu; var += dv * dv; }
        float r = rsqrtf(var * (1.0f / DIN) + 1e-5f);
        if (t < DIN) {
            float c  = (v[t] - mu) * r;
            float kn = c * g_st[t] + b_st[t];
            g_kdup[j * DIN + t] = make_float2(kn, kn);
            sv[t] = c * g_pp[t] + b_pp[t];
        }
    }
    __syncthreads();

    // p = Wv @ vln  (256 outputs, 2 per thread)
    #pragma unroll
    for (int rr = 0; rr < 2; rr++) {
        int row = t + rr * 128;
        float acc = 0.f;
        #pragma unroll
        for (int d = 0; d < DIN; d++) acc += Wv[row * DIN + d] * sv[d];
        sp[row] = acc;
    }
    __syncthreads();

    // h = Wo @ p  (28 outputs, 4-way split)
    if (t < 112) {
        int o = t >> 2, part = t & 3;
        float a = 0.f;
        int p0 = part * 64;
        #pragma unroll 8
        for (int p = p0; p < p0 + 64; p++) a += Wo[o * 256 + p] * sp[p];
        shp[o][part] = a;
    }
    __syncthreads();
    if (t < 28) hh[t] = shp[t][0] + shp[t][1] + shp[t][2] + shp[t][3];
    __syncthreads();

    // c = Wm @ h  (7 outputs, pad to 8)
    if (t < 8) {
        float a = 0.f;
        if (t < NC) {
            #pragma unroll
            for (int o = 0; o < 28; o++) a += Wm[t * 28 + o] * hh[o];
        }
        g_c8[j * 8 + t] = a;
    }
}

// ============================================================
// Main: 128 threads/block, 32 batch rows/block, 4 queries/thread.
// Two patterns (j, j+1) per iteration -> 4 independent FFMA2
// chains, enough ILP to hide LDS + compare latency.
// ============================================================
__global__ __launch_bounds__(128) void hopfield_main(
    const float* __restrict__ x,
    const float* __restrict__ g_sp, const float* __restrict__ b_sp,
    const float* __restrict__ bm,   const float* __restrict__ Wb,
    const float* __restrict__ bb,
    float* __restrict__ out, int B)
{
    __shared__ u64   sk[QN * DIN];   // 28672 B, (k,k) pairs
    __shared__ float swb[SB];
    __shared__ float sg[DIN], sb[DIN];
    __shared__ float sbm[8];
    __shared__ float sbb;

    int t = threadIdx.x;
    {
        const u64* kg = (const u64*)g_kdup;
        for (int i = t; i < QN * DIN; i += 128) sk[i] = kg[i];
        if (t < SB)  swb[t] = Wb[t];
        if (t < DIN) { sg[t] = g_sp[t]; sb[t] = b_sp[t]; }
        if (t < NC)  sbm[t] = bm[t];
        if (t == 0)  { sbm[7] = 0.f; sbb = bb[0]; }
    }
    __syncthreads();

    int brow = blockIdx.x * 32 + (t >> 2);
    bool valid = (brow < B);
    int b = valid ? brow : (B - 1);
    int s0 = (t & 3) * 4;                 // 4 consecutive bands per thread

    const float* xp = x + ((size_t)b * SB + s0) * DIN;

    // ---- LayerNorm 4 queries, pack pairwise into f32x2 ----
    u64 q2[2][DIN];
    #pragma unroll
    for (int pp = 0; pp < 2; pp++) {
        float qa[DIN], qb[DIN];
        #pragma unroll
        for (int half = 0; half < 2; half++) {
            float* q = half ? qb : qa;
            const float2* p2 = (const float2*)(xp + (2 * pp + half) * DIN);
            float v[DIN];
            #pragma unroll
            for (int i = 0; i < 7; i++) { float2 w = p2[i]; v[2*i] = w.x; v[2*i+1] = w.y; }
            float mu = 0.f;
            #pragma unroll
            for (int d = 0; d < DIN; d++) mu += v[d];
            mu *= (1.0f / DIN);
            float var = 0.f;
            #pragma unroll
            for (int d = 0; d < DIN; d++) { float dv = v[d] - mu; var += dv * dv; }
            float r = rsqrtf(var * (1.0f / DIN) + 1e-5f);
            #pragma unroll
            for (int d = 0; d < DIN; d++) q[d] = (v[d] - mu) * r * sg[d] + sb[d];
        }
        #pragma unroll
        for (int d = 0; d < DIN; d++) q2[pp][d] = pack2(qa[d], qb[d]);
    }

    // ---- argmax over 256 stored patterns, 2 patterns / iter ----
    float maxv[4]; int idx[4];
    #pragma unroll
    for (int p = 0; p < 4; p++) { maxv[p] = -CUDART_INF_F; idx[p] = 0; }

    const u64 z2 = pack2(0.f, 0.f);

    #pragma unroll 2
    for (int j = 0; j < QN; j += 2) {
        const ulonglong2* kp0 = (const ulonglong2*)(sk + j * DIN);
        const ulonglong2* kp1 = (const ulonglong2*)(sk + (j + 1) * DIN);
        u64 a0 = z2, a1 = z2;     // pattern j
        u64 b0 = z2, b1 = z2;     // pattern j+1
        #pragma unroll
        for (int i = 0; i < 7; i++) {
            ulonglong2 k0 = kp0[i];           // LDS.128 broadcast
            ulonglong2 k1 = kp1[i];
            a0 = fma2(k0.x, q2[0][2*i],   a0);
            a1 = fma2(k0.x, q2[1][2*i],   a1);
            b0 = fma2(k1.x, q2[0][2*i],   b0);
            b1 = fma2(k1.x, q2[1][2*i],   b1);
            a0 = fma2(k0.y, q2[0][2*i+1], a0);
            a1 = fma2(k0.y, q2[1][2*i+1], a1);
            b0 = fma2(k1.y, q2[0][2*i+1], b0);
            b1 = fma2(k1.y, q2[1][2*i+1], b1);
        }
        float lo, hi;
        unpack2(a0, lo, hi);
        if (lo > maxv[0]) { maxv[0] = lo; idx[0] = j; }
        if (hi > maxv[1]) { maxv[1] = hi; idx[1] = j; }
        unpack2(a1, lo, hi);
        if (lo > maxv[2]) { maxv[2] = lo; idx[2] = j; }
        if (hi > maxv[3]) { maxv[3] = hi; idx[3] = j; }
        unpack2(b0, lo, hi);
        if (lo > maxv[0]) { maxv[0] = lo; idx[0] = j + 1; }
        if (hi > maxv[1]) { maxv[1] = hi; idx[1] = j + 1; }
        unpack2(b1, lo, hi);
        if (lo > maxv[2]) { maxv[2] = lo; idx[2] = j + 1; }
        if (hi > maxv[3]) { maxv[3] = hi; idx[3] = j + 1; }
    }

    // ---- head: z[n] = sum_s Wb[s]*c[idx(s)][n] (+bias), softmax over 7 ----
    float zp[NC];
    #pragma unroll
    for (int n = 0; n < NC; n++) zp[n] = 0.f;
    #pragma unroll
    for (int p = 0; p < 4; p++) {
        int id = idx[p];
        float w = swb[s0 + p];
        const float4* cr = (const float4*)(g_c8 + id * 8);
        float4 c0 = __ldg(cr);
        float4 c1 = __ldg(cr + 1);
        zp[0] += w * c0.x; zp[1] += w * c0.y; zp[2] += w * c0.z; zp[3] += w * c0.w;
        zp[4] += w * c1.x; zp[5] += w * c1.y; zp[6] += w * c1.z;
    }
    // combine the 4 quarter-row threads (t..t^3, same b, same warp)
    #pragma unroll
    for (int n = 0; n < NC; n++) {
        zp[n] += __shfl_xor_sync(0xffffffffu, zp[n], 1);
        zp[n] += __shfl_xor_sync(0xffffffffu, zp[n], 2);
    }

    if (valid && ((t & 3) == 0)) {
        float sumWb = 0.f;
        #pragma unroll
        for (int s = 0; s < SB; s++) sumWb += swb[s];
        float z[NC], zmax = -CUDART_INF_F;
        #pragma unroll
        for (int n = 0; n < NC; n++) {
            z[n] = zp[n] + sbm[n] * sumWb + sbb;
            zmax = fmaxf(zmax, z[n]);
        }
        float es = 0.f;
        #pragma unroll
        for (int n = 0; n < NC; n++) { z[n] = expf(z[n] - zmax); es += z[n]; }
        float inv = 1.0f / es;
        float* op = out + (size_t)b * NC;
        #pragma unroll
        for (int n = 0; n < NC; n++) op[n] = z[n] * inv;
    }
}

// ============================================================
extern "C" void kernel_launch(void* const* d_in, const int* in_sizes, int n_in,
                              void* d_out, int out_size) {
    const float* x      = (const float*)d_in[0];
    const float* lookup = (const float*)d_in[1];
    const float* g_st   = (const float*)d_in[2];
    const float* b_st   = (const float*)d_in[3];
    const float* g_sp   = (const float*)d_in[4];
    const float* b_sp   = (const float*)d_in[5];
    const float* g_pp   = (const float*)d_in[6];
    const float* b_pp   = (const float*)d_in[7];
    const float* Wv     = (const float*)d_in[8];
    const float* Wo     = (const float*)d_in[9];
    const float* Wm     = (const float*)d_in[10];
    const float* bm     = (const float*)d_in[11];
    const float* Wb     = (const float*)d_in[12];
    const float* bb     = (const float*)d_in[13];
    float* out = (float*)d_out;

    int B = in_sizes[0] / (SB * DIN);

    prep_all<<<QN, 128>>>(lookup, g_st, b_st, g_pp, b_pp, Wv, Wo, Wm);
    hopfield_main<<<(B + 31) / 32, 128>>>(x, g_sp, b_sp, bm, Wb, bb, out, B);
}

// round 6
// speedup vs baseline: 1.2368x; 1.0626x over previous
#include <cuda_runtime.h>
#include <math_constants.h>

#define DIN 14
#define QN  256
#define SB  16
#define NC  7

typedef unsigned long long u64;

// ---- device scratch (no allocations allowed) ----
// pattern-PAIRED k storage: g_kp[jp*DIN+d] = (k[2jp][d], k[2jp+1][d])
__device__ float2 g_kp[(QN / 2) * DIN];
__device__ float  g_c8[QN * 8];       // c[j][n] = Wm@(Wo@(Wv@LNpp(lookup_j))), padded to 8

// ---- packed f32x2 helpers (Blackwell dual-rate FP32, FFMA2) ----
__device__ __forceinline__ u64 fma2(u64 a, u64 b, u64 c) {
    u64 d;
    asm("fma.rn.f32x2 %0, %1, %2, %3;" : "=l"(d) : "l"(a), "l"(b), "l"(c));
    return d;
}
__device__ __forceinline__ u64 pack2(float lo, float hi) {
    u64 r; asm("mov.b64 %0, {%1, %2};" : "=l"(r) : "f"(lo), "f"(hi)); return r;
}
__device__ __forceinline__ void unpack2(u64 v, float& lo, float& hi) {
    asm("mov.b64 {%0, %1}, %2;" : "=f"(lo), "=f"(hi) : "l"(v));
}

// ============================================================
// Fused prep: block j LayerNorms pattern j (both LN variants),
// then computes c8[j] = Wm@(Wo@(Wv@vln_j)) and writes g_kp[j/2].
// ============================================================
__global__ __launch_bounds__(128) void prep_all(
    const float* __restrict__ lookup,
    const float* __restrict__ g_st, const float* __restrict__ b_st,
    const float* __restrict__ g_pp, const float* __restrict__ b_pp,
    const float* __restrict__ Wv,   const float* __restrict__ Wo,
    const float* __restrict__ Wm)
{
    int j = blockIdx.x;
    int t = threadIdx.x;
    __shared__ float sv[DIN];       // vln_j
    __shared__ float sp[256];       // Wv @ vln
    __shared__ float shp[28][4];
    __shared__ float hh[28];

    // LN (every thread computes redundantly; thread<DIN writes)
    {
        float v[DIN];
        float mu = 0.f;
        #pragma unroll
        for (int d = 0; d < DIN; d++) { v[d] = lookup[j * DIN + d]; mu += v[d]; }
        mu *= (1.0f / DIN);
        float var = 0.f;
        #pragma unroll
        for (int d = 0; d < DIN; d++) { float dv = v[d] - mu; var += dv * dv; }
        float r = rsqrtf(var * (1.0f / DIN) + 1e-5f);
        if (t < DIN) {
            float c  = (v[t] - mu) * r;
            float kn = c * g_st[t] + b_st[t];
            // interleaved write into the pattern-pair slot
            ((float*)g_kp)[(((j >> 1) * DIN) + t) * 2 + (j & 1)] = kn;
            sv[t] = c * g_pp[t] + b_pp[t];
        }
    }
    __syncthreads();

    // p = Wv @ vln  (256 outputs, 2 per thread)
    #pragma unroll
    for (int rr = 0; rr < 2; rr++) {
        int row = t + rr * 128;
        float acc = 0.f;
        #pragma unroll
        for (int d = 0; d < DIN; d++) acc += Wv[row * DIN + d] * sv[d];
        sp[row] = acc;
    }
    __syncthreads();

    // h = Wo @ p  (28 outputs, 4-way split)
    if (t < 112) {
        int o = t >> 2, part = t & 3;
        float a = 0.f;
        int p0 = part * 64;
        #pragma unroll 8
        for (int p = p0; p < p0 + 64; p++) a += Wo[o * 256 + p] * sp[p];
        shp[o][part] = a;
    }
    __syncthreads();
    if (t < 28) hh[t] = shp[t][0] + shp[t][1] + shp[t][2] + shp[t][3];
    __syncthreads();

    // c = Wm @ h  (7 outputs, pad to 8)
    if (t < 8) {
        float a = 0.f;
        if (t < NC) {
            #pragma unroll
            for (int o = 0; o < 28; o++) a += Wm[t * 28 + o] * hh[o];
        }
        g_c8[j * 8 + t] = a;
    }
}

// ============================================================
// Main: 128 threads/block, 32 batch rows/block, 4 queries/thread.
// k stored pattern-paired (f32x2 of two patterns) -> NO smem
// duplication; queries duplicated (q,q) in registers once.
// Per jp-iteration: 7 LDS.128 (28 wf) feed 56 FFMA2 (112 fma-cyc)
// -> smem wavefront demand halved vs duplicated-k layout,
// balancing the fma pipe.
// ============================================================
__global__ __launch_bounds__(128, 3) void hopfield_main(
    const float* __restrict__ x,
    const float* __restrict__ g_sp, const float* __restrict__ b_sp,
    const float* __restrict__ bm,   const float* __restrict__ Wb,
    const float* __restrict__ bb,
    float* __restrict__ out, int B)
{
    __shared__ u64   sk[(QN / 2) * DIN];   // 14336 B, pattern pairs
    __shared__ float swb[SB];
    __shared__ float sg[DIN], sb[DIN];
    __shared__ float sbm[8];
    __shared__ float sbb;

    int t = threadIdx.x;
    {
        const u64* kg = (const u64*)g_kp;
        for (int i = t; i < (QN / 2) * DIN; i += 128) sk[i] = kg[i];
        if (t < SB)  swb[t] = Wb[t];
        if (t < DIN) { sg[t] = g_sp[t]; sb[t] = b_sp[t]; }
        if (t < NC)  sbm[t] = bm[t];
        if (t == 0)  { sbm[7] = 0.f; sbb = bb[0]; }
    }
    __syncthreads();

    int brow = blockIdx.x * 32 + (t >> 2);
    bool valid = (brow < B);
    int b = valid ? brow : (B - 1);
    int s0 = (t & 3) * 4;                 // 4 consecutive bands per thread

    const float* xp = x + ((size_t)b * SB + s0) * DIN;

    // ---- LayerNorm 4 queries; duplicate each into (q,q) u64 pairs ----
    u64 qd[4][DIN];
    #pragma unroll
    for (int qq = 0; qq < 4; qq++) {
        const float2* p2 = (const float2*)(xp + qq * DIN);
        float v[DIN];
        #pragma unroll
        for (int i = 0; i < 7; i++) { float2 w = p2[i]; v[2*i] = w.x; v[2*i+1] = w.y; }
        float mu = 0.f;
        #pragma unroll
        for (int d = 0; d < DIN; d++) mu += v[d];
        mu *= (1.0f / DIN);
        float var = 0.f;
        #pragma unroll
        for (int d = 0; d < DIN; d++) { float dv = v[d] - mu; var += dv * dv; }
        float r = rsqrtf(var * (1.0f / DIN) + 1e-5f);
        #pragma unroll
        for (int d = 0; d < DIN; d++) {
            float q = (v[d] - mu) * r * sg[d] + sb[d];
            qd[qq][d] = pack2(q, q);
        }
    }

    // ---- argmax over 256 patterns, one pattern-PAIR per iteration ----
    float maxv[4]; int idx[4];
    #pragma unroll
    for (int p = 0; p < 4; p++) { maxv[p] = -CUDART_INF_F; idx[p] = 0; }

    const u64 z2 = pack2(0.f, 0.f);

    #pragma unroll 2
    for (int jp = 0; jp < QN / 2; jp++) {
        const ulonglong2* kp = (const ulonglong2*)(sk + jp * DIN);
        // acc_q = (dot(q, k_2jp), dot(q, k_2jp+1))
        u64 a0 = z2, a1 = z2, a2 = z2, a3 = z2;
        #pragma unroll
        for (int i = 0; i < 7; i++) {
            ulonglong2 kk = kp[i];   // LDS.128: pattern-pair for dims 2i, 2i+1
            a0 = fma2(kk.x, qd[0][2*i],   a0);
            a1 = fma2(kk.x, qd[1][2*i],   a1);
            a2 = fma2(kk.x, qd[2][2*i],   a2);
            a3 = fma2(kk.x, qd[3][2*i],   a3);
            a0 = fma2(kk.y, qd[0][2*i+1], a0);
            a1 = fma2(kk.y, qd[1][2*i+1], a1);
            a2 = fma2(kk.y, qd[2][2*i+1], a2);
            a3 = fma2(kk.y, qd[3][2*i+1], a3);
        }
        int j0 = 2 * jp;
        float lo, hi;
        unpack2(a0, lo, hi);
        if (lo > maxv[0]) { maxv[0] = lo; idx[0] = j0; }
        if (hi > maxv[0]) { maxv[0] = hi; idx[0] = j0 + 1; }
        unpack2(a1, lo, hi);
        if (lo > maxv[1]) { maxv[1] = lo; idx[1] = j0; }
        if (hi > maxv[1]) { maxv[1] = hi; idx[1] = j0 + 1; }
        unpack2(a2, lo, hi);
        if (lo > maxv[2]) { maxv[2] = lo; idx[2] = j0; }
        if (hi > maxv[2]) { maxv[2] = hi; idx[2] = j0 + 1; }
        unpack2(a3, lo, hi);
        if (lo > maxv[3]) { maxv[3] = lo; idx[3] = j0; }
        if (hi > maxv[3]) { maxv[3] = hi; idx[3] = j0 + 1; }
    }

    // ---- head: z[n] = sum_s Wb[s]*c[idx(s)][n] (+bias), softmax over 7 ----
    float zp[NC];
    #pragma unroll
    for (int n = 0; n < NC; n++) zp[n] = 0.f;
    #pragma unroll
    for (int p = 0; p < 4; p++) {
        int id = idx[p];
        float w = swb[s0 + p];
        const float4* cr = (const float4*)(g_c8 + id * 8);
        float4 c0 = __ldg(cr);
        float4 c1 = __ldg(cr + 1);
        zp[0] += w * c0.x; zp[1] += w * c0.y; zp[2] += w * c0.z; zp[3] += w * c0.w;
        zp[4] += w * c1.x; zp[5] += w * c1.y; zp[6] += w * c1.z;
    }
    // combine the 4 quarter-row threads (t..t^3, same b, same warp)
    #pragma unroll
    for (int n = 0; n < NC; n++) {
        zp[n] += __shfl_xor_sync(0xffffffffu, zp[n], 1);
        zp[n] += __shfl_xor_sync(0xffffffffu, zp[n], 2);
    }

    if (valid && ((t & 3) == 0)) {
        float sumWb = 0.f;
        #pragma unroll
        for (int s = 0; s < SB; s++) sumWb += swb[s];
        float z[NC], zmax = -CUDART_INF_F;
        #pragma unroll
        for (int n = 0; n < NC; n++) {
            z[n] = zp[n] + sbm[n] * sumWb + sbb;
            zmax = fmaxf(zmax, z[n]);
        }
        float es = 0.f;
        #pragma unroll
        for (int n = 0; n < NC; n++) { z[n] = expf(z[n] - zmax); es += z[n]; }
        float inv = 1.0f / es;
        float* op = out + (size_t)b * NC;
        #pragma unroll
        for (int n = 0; n < NC; n++) op[n] = z[n] * inv;
    }
}

// ============================================================
extern "C" void kernel_launch(void* const* d_in, const int* in_sizes, int n_in,
                              void* d_out, int out_size) {
    const float* x      = (const float*)d_in[0];
    const float* lookup = (const float*)d_in[1];
    const float* g_st   = (const float*)d_in[2];
    const float* b_st   = (const float*)d_in[3];
    const float* g_sp   = (const float*)d_in[4];
    const float* b_sp   = (const float*)d_in[5];
    const float* g_pp   = (const float*)d_in[6];
    const float* b_pp   = (const float*)d_in[7];
    const float* Wv     = (const float*)d_in[8];
    const float* Wo     = (const float*)d_in[9];
    const float* Wm     = (const float*)d_in[10];
    const float* bm     = (const float*)d_in[11];
    const float* Wb     = (const float*)d_in[12];
    const float* bb     = (const float*)d_in[13];
    float* out = (float*)d_out;

    int B = in_sizes[0] / (SB * DIN);

    prep_all<<<QN, 128>>>(lookup, g_st, b_st, g_pp, b_pp, Wv, Wo, Wm);
    hopfield_main<<<(B + 31) / 32, 128>>>(x, g_sp, b_sp, bm, Wb, bb, out, B);
}

// round 8
// speedup vs baseline: 1.2874x; 1.0410x over previous
#include <cuda_runtime.h>
#include <math_constants.h>

#define DIN 14
#define QN  256
#define SB  16
#define NC  7

typedef unsigned long long u64;

// ---- device scratch (no allocations allowed) ----
// pattern-PAIRED k storage: g_kp[jp*DIN+d] = (k[2jp][d], k[2jp+1][d])
__device__ float2 g_kp[(QN / 2) * DIN];
__device__ float  g_c8[QN * 8];       // c[j][n] = Wm@(Wo@(Wv@LNpp(lookup_j))), padded to 8

// ---- packed f32x2 helpers (Blackwell dual-rate FP32, FFMA2) ----
__device__ __forceinline__ u64 fma2(u64 a, u64 b, u64 c) {
    u64 d;
    asm("fma.rn.f32x2 %0, %1, %2, %3;" : "=l"(d) : "l"(a), "l"(b), "l"(c));
    return d;
}
__device__ __forceinline__ u64 pack2(float lo, float hi) {
    u64 r; asm("mov.b64 %0, {%1, %2};" : "=l"(r) : "f"(lo), "f"(hi)); return r;
}
__device__ __forceinline__ void unpack2(u64 v, float& lo, float& hi) {
    asm("mov.b64 {%0, %1}, %2;" : "=f"(lo), "=f"(hi) : "l"(v));
}

// ============================================================
// Fused prep: block j LayerNorms pattern j (both LN variants),
// then computes c8[j] = Wm@(Wo@(Wv@vln_j)) and writes g_kp[j/2].
// ============================================================
__global__ __launch_bounds__(128) void prep_all(
    const float* __restrict__ lookup,
    const float* __restrict__ g_st, const float* __restrict__ b_st,
    const float* __restrict__ g_pp, const float* __restrict__ b_pp,
    const float* __restrict__ Wv,   const float* __restrict__ Wo,
    const float* __restrict__ Wm)
{
    int j = blockIdx.x;
    int t = threadIdx.x;
    __shared__ float sv[DIN];       // vln_j
    __shared__ float sp[256];       // Wv @ vln
    __shared__ float shp[28][4];
    __shared__ float hh[28];

    // LN (every thread computes redundantly; thread<DIN writes)
    {
        float v[DIN];
        float mu = 0.f;
        #pragma unroll
        for (int d = 0; d < DIN; d++) { v[d] = lookup[j * DIN + d]; mu += v[d]; }
        mu *= (1.0f / DIN);
        float var = 0.f;
        #pragma unroll
        for (int d = 0; d < DIN; d++) { float dv = v[d] - mu; var += dv * dv; }
        float r = rsqrtf(var * (1.0f / DIN) + 1e-5f);
        if (t < DIN) {
            float c  = (v[t] - mu) * r;
            float kn = c * g_st[t] + b_st[t];
            // interleaved write into the pattern-pair slot
            ((float*)g_kp)[(((j >> 1) * DIN) + t) * 2 + (j & 1)] = kn;
            sv[t] = c * g_pp[t] + b_pp[t];
        }
    }
    __syncthreads();

    // p = Wv @ vln  (256 outputs, 2 per thread)
    #pragma unroll
    for (int rr = 0; rr < 2; rr++) {
        int row = t + rr * 128;
        float acc = 0.f;
        #pragma unroll
        for (int d = 0; d < DIN; d++) acc += Wv[row * DIN + d] * sv[d];
        sp[row] = acc;
    }
    __syncthreads();

    // h = Wo @ p  (28 outputs, 4-way split)
    if (t < 112) {
        int o = t >> 2, part = t & 3;
        float a = 0.f;
        int p0 = part * 64;
        #pragma unroll 8
        for (int p = p0; p < p0 + 64; p++) a += Wo[o * 256 + p] * sp[p];
        shp[o][part] = a;
    }
    __syncthreads();
    if (t < 28) hh[t] = shp[t][0] + shp[t][1] + shp[t][2] + shp[t][3];
    __syncthreads();

    // c = Wm @ h  (7 outputs, pad to 8)
    if (t < 8) {
        float a = 0.f;
        if (t < NC) {
            #pragma unroll
            for (int o = 0; o < 28; o++) a += Wm[t * 28 + o] * hh[o];
        }
        g_c8[j * 8 + t] = a;
    }
}

// ============================================================
// Main: 128 threads/block, 32 batch rows/block, 4 queries/thread.
// k pattern-paired in smem (no duplication); queries duplicated
// (q,q) in registers. Argmax restructured so the loop-carried
// dependence is a single FMNMX (4 cyc), FSETP/SEL off-path.
// launch_bounds(128,4): 128-reg cap -> 4 blocks/SM (16 warps).
// ============================================================
__global__ __launch_bounds__(128, 4) void hopfield_main(
    const float* __restrict__ x,
    const float* __restrict__ g_sp, const float* __restrict__ b_sp,
    const float* __restrict__ bm,   const float* __restrict__ Wb,
    const float* __restrict__ bb,
    float* __restrict__ out, int B)
{
    __shared__ u64   sk[(QN / 2) * DIN];   // 14336 B, pattern pairs
    __shared__ float swb[SB];
    __shared__ float sg[DIN], sb[DIN];
    __shared__ float sbm[8];
    __shared__ float sbb;

    int t = threadIdx.x;
    {
        const u64* kg = (const u64*)g_kp;
        for (int i = t; i < (QN / 2) * DIN; i += 128) sk[i] = kg[i];
        if (t < SB)  swb[t] = Wb[t];
        if (t < DIN) { sg[t] = g_sp[t]; sb[t] = b_sp[t]; }
        if (t < NC)  sbm[t] = bm[t];
        if (t == 0)  { sbm[7] = 0.f; sbb = bb[0]; }
    }
    __syncthreads();

    int brow = blockIdx.x * 32 + (t >> 2);
    bool valid = (brow < B);
    int b = valid ? brow : (B - 1);
    int s0 = (t & 3) * 4;                 // 4 consecutive bands per thread

    const float* xp = x + ((size_t)b * SB + s0) * DIN;

    // ---- LayerNorm 4 queries; duplicate each into (q,q) u64 pairs ----
    u64 qd[4][DIN];
    #pragma unroll
    for (int qq = 0; qq < 4; qq++) {
        const float2* p2 = (const float2*)(xp + qq * DIN);
        float v[DIN];
        #pragma unroll
        for (int i = 0; i < 7; i++) { float2 w = p2[i]; v[2*i] = w.x; v[2*i+1] = w.y; }
        float mu = 0.f;
        #pragma unroll
        for (int d = 0; d < DIN; d++) mu += v[d];
        mu *= (1.0f / DIN);
        float var = 0.f;
        #pragma unroll
        for (int d = 0; d < DIN; d++) { float dv = v[d] - mu; var += dv * dv; }
        float r = rsqrtf(var * (1.0f / DIN) + 1e-5f);
        #pragma unroll
        for (int d = 0; d < DIN; d++) {
            float q = (v[d] - mu) * r * sg[d] + sb[d];
            qd[qq][d] = pack2(q, q);
        }
    }

    // ---- argmax over 256 patterns, one pattern-PAIR per iteration ----
    float maxv[4]; int idx[4];
    #pragma unroll
    for (int p = 0; p < 4; p++) { maxv[p] = -CUDART_INF_F; idx[p] = 0; }

    const u64 z2 = pack2(0.f, 0.f);

    #pragma unroll 2
    for (int jp = 0; jp < QN / 2; jp++) {
        const ulonglong2* kp = (const ulonglong2*)(sk + jp * DIN);
        // acc_q = (dot(q, k_2jp), dot(q, k_2jp+1))
        u64 a0 = z2, a1 = z2, a2 = z2, a3 = z2;
        #pragma unroll
        for (int i = 0; i < 7; i++) {
            ulonglong2 kk = kp[i];   // LDS.128: pattern-pair for dims 2i, 2i+1
            a0 = fma2(kk.x, qd[0][2*i],   a0);
            a1 = fma2(kk.x, qd[1][2*i],   a1);
            a2 = fma2(kk.x, qd[2][2*i],   a2);
            a3 = fma2(kk.x, qd[3][2*i],   a3);
            a0 = fma2(kk.y, qd[0][2*i+1], a0);
            a1 = fma2(kk.y, qd[1][2*i+1], a1);
            a2 = fma2(kk.y, qd[2][2*i+1], a2);
            a3 = fma2(kk.y, qd[3][2*i+1], a3);
        }
        int j0 = 2 * jp;
        // Carried dep per query = one FMNMX (lat 4). FSETPs off-path.
        {
            float lo, hi; unpack2(a0, lo, hi);
            float pm   = fmaxf(lo, hi);
            int   jsel = (hi > lo) ? (j0 + 1) : j0;
            bool  upd  = pm > maxv[0];
            maxv[0] = fmaxf(maxv[0], pm);
            idx[0]  = upd ? jsel : idx[0];
        }
        {
            float lo, hi; unpack2(a1, lo, hi);
            float pm   = fmaxf(lo, hi);
            int   jsel = (hi > lo) ? (j0 + 1) : j0;
            bool  upd  = pm > maxv[1];
            maxv[1] = fmaxf(maxv[1], pm);
            idx[1]  = upd ? jsel : idx[1];
        }
        {
            float lo, hi; unpack2(a2, lo, hi);
            float pm   = fmaxf(lo, hi);
            int   jsel = (hi > lo) ? (j0 + 1) : j0;
            bool  upd  = pm > maxv[2];
            maxv[2] = fmaxf(maxv[2], pm);
            idx[2]  = upd ? jsel : idx[2];
        }
        {
            float lo, hi; unpack2(a3, lo, hi);
            float pm   = fmaxf(lo, hi);
            int   jsel = (hi > lo) ? (j0 + 1) : j0;
            bool  upd  = pm > maxv[3];
            maxv[3] = fmaxf(maxv[3], pm);
            idx[3]  = upd ? jsel : idx[3];
        }
    }

    // ---- head: z[n] = sum_s Wb[s]*c[idx(s)][n] (+bias), softmax over 7 ----
    float zp[NC];
    #pragma unroll
    for (int n = 0; n < NC; n++) zp[n] = 0.f;
    #pragma unroll
    for (int p = 0; p < 4; p++) {
        int id = idx[p];
        float w = swb[s0 + p];
        const float4* cr = (const float4*)(g_c8 + id * 8);
        float4 c0 = __ldg(cr);
        float4 c1 = __ldg(cr + 1);
        zp[0] += w * c0.x; zp[1] += w * c0.y; zp[2] += w * c0.z; zp[3] += w * c0.w;
        zp[4] += w * c1.x; zp[5] += w * c1.y; zp[6] += w * c1.z;
    }
    // combine the 4 quarter-row threads (t..t^3, same b, same warp)
    #pragma unroll
    for (int n = 0; n < NC; n++) {
        zp[n] += __shfl_xor_sync(0xffffffffu, zp[n], 1);
        zp[n] += __shfl_xor_sync(0xffffffffu, zp[n], 2);
    }

    if (valid && ((t & 3) == 0)) {
        float sumWb = 0.f;
        #pragma unroll
        for (int s = 0; s < SB; s++) sumWb += swb[s];
        float z[NC], zmax = -CUDART_INF_F;
        #pragma unroll
        for (int n = 0; n < NC; n++) {
            z[n] = zp[n] + sbm[n] * sumWb + sbb;
            zmax = fmaxf(zmax, z[n]);
        }
        float es = 0.f;
        #pragma unroll
        for (int n = 0; n < NC; n++) { z[n] = expf(z[n] - zmax); es += z[n]; }
        float inv = 1.0f / es;
        float* op = out + (size_t)b * NC;
        #pragma unroll
        for (int n = 0; n < NC; n++) op[n] = z[n] * inv;
    }
}

// ============================================================
extern "C" void kernel_launch(void* const* d_in, const int* in_sizes, int n_in,
                              void* d_out, int out_size) {
    const float* x      = (const float*)d_in[0];
    const float* lookup = (const float*)d_in[1];
    const float* g_st   = (const float*)d_in[2];
    const float* b_st   = (const float*)d_in[3];
    const float* g_sp   = (const float*)d_in[4];
    const float* b_sp   = (const float*)d_in[5];
    const float* g_pp   = (const float*)d_in[6];
    const float* b_pp   = (const float*)d_in[7];
    const float* Wv     = (const float*)d_in[8];
    const float* Wo     = (const float*)d_in[9];
    const float* Wm     = (const float*)d_in[10];
    const float* bm     = (const float*)d_in[11];
    const float* Wb     = (const float*)d_in[12];
    const float* bb     = (const float*)d_in[13];
    float* out = (float*)d_out;

    int B = in_sizes[0] / (SB * DIN);

    prep_all<<<QN, 128>>>(lookup, g_st, b_st, g_pp, b_pp, Wv, Wo, Wm);
    hopfield_main<<<(B + 31) / 32, 128>>>(x, g_sp, b_sp, bm, Wb, bb, out, B);
}